// round 14
// baseline (speedup 1.0000x reference)
#include <cuda_runtime.h>
#include <cuda_bf16.h>
#include <cuda_fp16.h>
#include <math.h>
#include <stdint.h>

// Problem constants (fixed by the reference)
#define BATCH   8
#define SEQ     4096
#define DMODEL  1024
#define DSTATE  64
#define PROJ_E  192          // effective rows after folding the pair-mean into W1
#define NCHUNK  64
#define CLEN    64           // SEQ / NCHUNK
#define M_ROWS  (BATCH*SEQ)  // 32768

// ---------------------------------------------------------------------------
// Scratch (static __device__ globals; no allocation in kernel_launch)
// ---------------------------------------------------------------------------
__device__ __half g_xcf[(size_t)M_ROWS * DMODEL];  // conv out, fp16 (67 MB)
__device__ __half g_w1f[(size_t)PROJ_E * DMODEL];  // pre-averaged W1, fp16
__device__ __half g_w2f[(size_t)DMODEL * DSTATE];  // W2, fp16
__device__ __half g_yf [(size_t)M_ROWS * DSTATE];  // y, fp16 (4 MB)
__device__ float g_b1e [PROJ_E];
__device__ float g_proj[(size_t)M_ROWS * PROJ_E];  // 25 MB
__device__ float g_Abar[(size_t)M_ROWS * DSTATE];
__device__ float g_Bbar[(size_t)M_ROWS * DSTATE];
__device__ float g_Cm  [(size_t)M_ROWS * DSTATE];
__device__ float g_P   [BATCH * NCHUNK * DSTATE];
__device__ float g_H   [BATCH * NCHUNK * DSTATE];
__device__ float g_Hin [BATCH * NCHUNK * DSTATE];

// ---------------------------------------------------------------------------
// PTX helpers (legacy tensor path: ldmatrix + mma.sync, valid on sm_100 base)
// ---------------------------------------------------------------------------
__device__ __forceinline__ uint32_t smem_u32(const void* p) {
    uint32_t a;
    asm("{ .reg .u64 t; cvta.to.shared.u64 t, %1; cvt.u32.u64 %0, t; }" : "=r"(a) : "l"(p));
    return a;
}
__device__ __forceinline__ void ldsm_x4(uint32_t* r, uint32_t addr) {
    asm volatile("ldmatrix.sync.aligned.m8n8.x4.shared.b16 {%0,%1,%2,%3}, [%4];"
        : "=r"(r[0]), "=r"(r[1]), "=r"(r[2]), "=r"(r[3]) : "r"(addr));
}
__device__ __forceinline__ void mma_f16(float* d, const uint32_t* a, const uint32_t* b) {
    asm volatile("mma.sync.aligned.m16n8k16.row.col.f32.f16.f16.f32 "
        "{%0,%1,%2,%3}, {%4,%5,%6,%7}, {%8,%9}, {%0,%1,%2,%3};"
        : "+f"(d[0]), "+f"(d[1]), "+f"(d[2]), "+f"(d[3])
        : "r"(a[0]), "r"(a[1]), "r"(a[2]), "r"(a[3]), "r"(b[0]), "r"(b[1]));
}
__device__ __forceinline__ void cp16(uint32_t saddr, const void* gaddr) {
    asm volatile("cp.async.cg.shared.global [%0], [%1], 16;" :: "r"(saddr), "l"(gaddr) : "memory");
}
#define CP_COMMIT()  asm volatile("cp.async.commit_group;" ::: "memory")
#define CP_WAIT(n)   asm volatile("cp.async.wait_group %0;" :: "n"(n) : "memory")
// SW128 swizzle on byte offsets (rows of 128 bytes)
#define SWZ(off)   ((uint32_t)(off) ^ ((((uint32_t)(off)) >> 3) & 0x70))

// ---------------------------------------------------------------------------
// 1. Depthwise conv (k=4, pad=(1,1)), last timestep zeroed. Emits fp16.
// ---------------------------------------------------------------------------
__global__ void conv_kernel(const float* __restrict__ x,
                            const float* __restrict__ cw,
                            const float* __restrict__ cb)
{
    const int D4  = DMODEL / 4;
    int idx = blockIdx.x * blockDim.x + threadIdx.x;
    if (idx >= BATCH * SEQ * D4) return;

    int d4 = idx % D4;
    int bt = idx / D4;
    int t  = bt % SEQ;
    int b  = bt / SEQ;
    int d  = d4 * 4;

    float4 acc;
    if (t == SEQ - 1) {
        acc = make_float4(0.f, 0.f, 0.f, 0.f);
    } else {
        acc = *(const float4*)(cb + d);
        float4 w0 = *(const float4*)(cw + (size_t)(d + 0) * 4);
        float4 w1 = *(const float4*)(cw + (size_t)(d + 1) * 4);
        float4 w2 = *(const float4*)(cw + (size_t)(d + 2) * 4);
        float4 w3 = *(const float4*)(cw + (size_t)(d + 3) * 4);
        const float* wa0 = (const float*)&w0;
        const float* wa1 = (const float*)&w1;
        const float* wa2 = (const float*)&w2;
        const float* wa3 = (const float*)&w3;
        const float* xb = x + (size_t)b * SEQ * DMODEL + d;
        #pragma unroll
        for (int j = 0; j < 4; j++) {
            int tt = t - 1 + j;
            if (tt < 0 || tt >= SEQ) continue;
            float4 xv = *(const float4*)(xb + (size_t)tt * DMODEL);
            acc.x = fmaf(wa0[j], xv.x, acc.x);
            acc.y = fmaf(wa1[j], xv.y, acc.y);
            acc.z = fmaf(wa2[j], xv.z, acc.z);
            acc.w = fmaf(wa3[j], xv.w, acc.w);
        }
    }
    __half h[4];
    h[0] = __float2half_rn(acc.x);
    h[1] = __float2half_rn(acc.y);
    h[2] = __float2half_rn(acc.z);
    h[3] = __float2half_rn(acc.w);
    *(uint2*)(g_xcf + (size_t)bt * DMODEL + d) = *(const uint2*)h;
}

// ---------------------------------------------------------------------------
// 1b. Weight prep: fold pair-mean into W1 (320 -> 192 rows) as fp16;
//     W2 as fp16; build effective bias.
// ---------------------------------------------------------------------------
#define N_W1E (PROJ_E * DMODEL)
#define N_W2  (DMODEL * DSTATE)
__global__ void wprep_kernel(const float* __restrict__ w1,
                             const float* __restrict__ b1,
                             const float* __restrict__ w2)
{
    int i = blockIdx.x * blockDim.x + threadIdx.x;
    if (i < N_W1E) {
        int n = i / DMODEL, k = i % DMODEL;
        float v;
        if (n < 64) {
            v = w1[(size_t)n * DMODEL + k];
        } else if (n < 128) {
            int m = 64 + 2 * (n - 64);
            v = 0.5f * (w1[(size_t)m * DMODEL + k] + w1[(size_t)(m + 1) * DMODEL + k]);
        } else {
            int m = 192 + 2 * (n - 128);
            v = 0.5f * (w1[(size_t)m * DMODEL + k] + w1[(size_t)(m + 1) * DMODEL + k]);
        }
        g_w1f[i] = __float2half_rn(v);
    } else if (i < N_W1E + N_W2) {
        int j = i - N_W1E;
        g_w2f[j] = __float2half_rn(w2[j]);
    }
    if (i < PROJ_E) {
        float bv;
        if (i < 64)       bv = b1[i];
        else if (i < 128) bv = 0.5f * (b1[64 + 2 * (i - 64)] + b1[65 + 2 * (i - 64)]);
        else              bv = 0.5f * (b1[192 + 2 * (i - 128)] + b1[193 + 2 * (i - 128)]);
        g_b1e[i] = bv;
    }
}

// ---------------------------------------------------------------------------
// 2. GEMM1 (fp16, single pass): proj[M,192] = xc[M,1024] @ W1eff[192,1024]^T + b1eff
//    CTA tile 128x192, 8 warps (2m x 4n), warp tile 64x48.
//    K-chunks of 64 (128B rows, SW128), 4-stage cp.async pipeline.
// ---------------------------------------------------------------------------
#define G1_A 0
#define G1_B 16384
#define G1_STAGE 40960           // A 16KB + B 24KB
#define G1_SMEM (G1_STAGE * 4)   // 163840 bytes

__global__ __launch_bounds__(256)
void gemm1_mma(const float* __restrict__ bias)
{
    extern __shared__ char smem[];
    const uint32_t sb = smem_u32(smem);
    const int tid  = threadIdx.x;
    const int lane = tid & 31;
    const int wid  = tid >> 5;
    const int wm   = (wid >> 2) * 64;   // 0 / 64
    const int wn   = (wid & 3) * 48;    // 0,48,96,144
    const int bm   = blockIdx.x * 128;

    float d[4][6][4];
    #pragma unroll
    for (int i = 0; i < 4; i++)
        #pragma unroll
        for (int j = 0; j < 6; j++)
            #pragma unroll
            for (int c = 0; c < 4; c++) d[i][j][c] = 0.f;

    auto load_chunk = [&](int c) {
        const int k0 = c * 64;                  // fp16 elem offset in K
        const uint32_t s0 = sb + (c & 3) * G1_STAGE;
        // A: 128 rows x 128B (1024 16B-units; 4 per thread)
        #pragma unroll
        for (int i = tid; i < 1024; i += 256) {
            int r = i >> 3, cB = (i & 7) << 4;
            size_t go = (size_t)(bm + r) * DMODEL + k0 + (cB >> 1);
            uint32_t so = SWZ(r * 128 + cB);
            cp16(s0 + G1_A + so, g_xcf + go);
        }
        // B: 192 rows x 128B (1536 units; 6 per thread)
        #pragma unroll
        for (int i = tid; i < 1536; i += 256) {
            int r = i >> 3, cB = (i & 7) << 4;
            size_t go = (size_t)r * DMODEL + k0 + (cB >> 1);
            uint32_t so = SWZ(r * 128 + cB);
            cp16(s0 + G1_B + so, g_w1f + go);
        }
        CP_COMMIT();
    };

    load_chunk(0);
    load_chunk(1);
    load_chunk(2);

    const int T = 16;
    for (int c = 0; c < T; c++) {
        if (c + 3 < T)      { CP_WAIT(2); }
        else if (c + 2 < T) { CP_WAIT(1); }
        else                { CP_WAIT(0); }
        __syncthreads();
        if (c + 3 < T) load_chunk(c + 3);

        const uint32_t sA = sb + (c & 3) * G1_STAGE;
        #pragma unroll
        for (int ks = 0; ks < 4; ks++) {
            const int kb = ks * 32;     // byte col of this k16 step
            const int mi = lane >> 3;
            const int col = kb + ((mi >> 1) << 4);
            // B fragments (6 n8 atoms)
            uint32_t bh[6][2];
            #pragma unroll
            for (int jj = 0; jj < 3; jj++) {
                int row = wn + jj * 16 + ((mi & 1) << 3) + (lane & 7);
                uint32_t so = SWZ(row * 128 + col);
                uint32_t r4[4];
                ldsm_x4(r4, sA + G1_B + so);
                bh[2*jj][0] = r4[0]; bh[2*jj+1][0] = r4[1];
                bh[2*jj][1] = r4[2]; bh[2*jj+1][1] = r4[3];
            }
            // A fragments (4 m16 atoms)
            uint32_t ah[4][4];
            #pragma unroll
            for (int i = 0; i < 4; i++) {
                int row = wm + i * 16 + ((mi & 1) << 3) + (lane & 7);
                uint32_t so = SWZ(row * 128 + col);
                ldsm_x4(ah[i], sA + G1_A + so);
            }
            #pragma unroll
            for (int i = 0; i < 4; i++)
                #pragma unroll
                for (int j = 0; j < 6; j++) mma_f16(d[i][j], ah[i], bh[j]);
        }
    }

    // Epilogue (proj row stride = 192)
    const int gid = lane >> 2, tig = lane & 3;
    #pragma unroll
    for (int i = 0; i < 4; i++) {
        int row0 = bm + wm + i * 16 + gid;
        #pragma unroll
        for (int j = 0; j < 6; j++) {
            int col = wn + j * 8 + tig * 2;
            float b0 = bias[col], b1 = bias[col + 1];
            float2 v0 = make_float2(d[i][j][0] + b0, d[i][j][1] + b1);
            float2 v1 = make_float2(d[i][j][2] + b0, d[i][j][3] + b1);
            *(float2*)(g_proj + (size_t)row0 * PROJ_E + col)       = v0;
            *(float2*)(g_proj + (size_t)(row0 + 8) * PROJ_E + col) = v1;
        }
    }
}

// ---------------------------------------------------------------------------
// 2b. GEMM2 (fp16, single pass): out[M,1024] = y[M,64] @ W2[1024,64]^T + b2
//    CTA tile 128x128, K=64 in one shot. 8 warps (2m x 4n), warp tile 64x32.
// ---------------------------------------------------------------------------
#define G2_A 0
#define G2_B 16384
#define G2_SMEM 32768

__global__ __launch_bounds__(256)
void gemm2_mma(const float* __restrict__ bias, float* __restrict__ out)
{
    extern __shared__ char smem[];
    const uint32_t sb = smem_u32(smem);
    const int tid  = threadIdx.x;
    const int lane = tid & 31;
    const int wid  = tid >> 5;
    const int wm   = (wid >> 2) * 64;
    const int wn   = (wid & 3) * 32;
    const int bm   = blockIdx.y * 128;
    const int bn   = blockIdx.x * 128;

    float d[4][4][4];
    #pragma unroll
    for (int i = 0; i < 4; i++)
        #pragma unroll
        for (int j = 0; j < 4; j++)
            #pragma unroll
            for (int c = 0; c < 4; c++) d[i][j][c] = 0.f;

    // A tile: 128 rows x 128B (64 fp16)
    #pragma unroll
    for (int i = tid; i < 1024; i += 256) {
        int r = i >> 3, cB = (i & 7) << 4;
        size_t go = (size_t)(bm + r) * DSTATE + (cB >> 1);
        uint32_t so = SWZ(r * 128 + cB);
        cp16(sb + G2_A + so, g_yf + go);
    }
    // B tile: 128 rows x 128B
    #pragma unroll
    for (int i = tid; i < 1024; i += 256) {
        int r = i >> 3, cB = (i & 7) << 4;
        size_t go = (size_t)(bn + r) * DSTATE + (cB >> 1);
        uint32_t so = SWZ(r * 128 + cB);
        cp16(sb + G2_B + so, g_w2f + go);
    }
    CP_COMMIT();
    CP_WAIT(0);
    __syncthreads();

    #pragma unroll
    for (int ks = 0; ks < 4; ks++) {
        const int kb = ks * 32;
        const int mi = lane >> 3;
        uint32_t bh[4][2];
        {
            int row = wn + ((mi & 1) << 3) + (lane & 7);
            int col = kb + ((mi >> 1) << 4);
            uint32_t so = SWZ(row * 128 + col);
            uint32_t r4[4];
            ldsm_x4(r4, sb + G2_B + so);
            bh[0][0] = r4[0]; bh[1][0] = r4[1]; bh[0][1] = r4[2]; bh[1][1] = r4[3];
            uint32_t so2 = SWZ((row + 16) * 128 + col);
            ldsm_x4(r4, sb + G2_B + so2);
            bh[2][0] = r4[0]; bh[3][0] = r4[1]; bh[2][1] = r4[2]; bh[3][1] = r4[3];
        }
        uint32_t ah[4][4];
        #pragma unroll
        for (int i = 0; i < 4; i++) {
            int row = wm + i * 16 + ((mi & 1) << 3) + (lane & 7);
            int col = kb + ((mi >> 1) << 4);
            uint32_t so = SWZ(row * 128 + col);
            ldsm_x4(ah[i], sb + G2_A + so);
        }
        #pragma unroll
        for (int i = 0; i < 4; i++)
            #pragma unroll
            for (int j = 0; j < 4; j++) mma_f16(d[i][j], ah[i], bh[j]);
    }

    const int gid = lane >> 2, tig = lane & 3;
    #pragma unroll
    for (int i = 0; i < 4; i++) {
        int row0 = bm + wm + i * 16 + gid;
        #pragma unroll
        for (int j = 0; j < 4; j++) {
            int col = bn + wn + j * 8 + tig * 2;
            float b0 = bias[col], b1 = bias[col + 1];
            float2 v0 = make_float2(d[i][j][0] + b0, d[i][j][1] + b1);
            float2 v1 = make_float2(d[i][j][2] + b0, d[i][j][3] + b1);
            *(float2*)(out + (size_t)row0 * DMODEL + col)       = v0;
            *(float2*)(out + (size_t)(row0 + 8) * DMODEL + col) = v1;
        }
    }
}

// ---------------------------------------------------------------------------
// 3. Elementwise SSM params (proj layout: [delta(64) | Bm(64) | Cm(64)])
// ---------------------------------------------------------------------------
__global__ void elem_kernel(const float* __restrict__ Alog)
{
    int idx = blockIdx.x * blockDim.x + threadIdx.x;
    if (idx >= M_ROWS * DSTATE) return;
    int s  = idx % DSTATE;
    int bt = idx / DSTATE;

    const float* p = g_proj + (size_t)bt * PROJ_E;
    float delta = p[s];
    float Bm    = p[64 + s];
    float Cm    = p[128 + s];

    float A = -expf(Alog[s]);
    float sp = fmaxf(delta, 0.f) + log1pf(expf(-fabsf(delta)));
    float dA = sp * A;
    float Abar = expf(dA);

    float scale;
    if (fabsf(A) < 1e-4f) {
        scale = 1.f + dA * 0.5f + dA * dA * (1.f / 6.f);
    } else {
        scale = (Abar - 1.f) / A;
    }

    g_Abar[idx] = Abar;
    g_Bbar[idx] = scale * Bm;
    g_Cm[idx]   = Cm;
}

// ---------------------------------------------------------------------------
// 4. Chunked linear-recurrence scan
// ---------------------------------------------------------------------------
__global__ void scanA_kernel()
{
    int b = blockIdx.x / NCHUNK;
    int c = blockIdx.x % NCHUNK;
    int s = threadIdx.x;
    size_t base = ((size_t)b * SEQ + (size_t)c * CLEN) * DSTATE + s;
    float h = 0.f, p = 1.f;
    #pragma unroll 4
    for (int i = 0; i < CLEN; i++) {
        float a  = g_Abar[base + (size_t)i * DSTATE];
        float bb = g_Bbar[base + (size_t)i * DSTATE];
        h = fmaf(a, h, bb);
        p *= a;
    }
    int o = (b * NCHUNK + c) * DSTATE + s;
    g_P[o] = p;
    g_H[o] = h;
}

__global__ void scanB_kernel()
{
    int b = blockIdx.x;
    int s = threadIdx.x;
    int base = b * NCHUNK * DSTATE + s;
    float h  = 0.f;
    float pc = g_P[base];
    float hc = g_H[base];
    for (int c = 0; c < NCHUNK; c++) {
        float pn = 0.f, hn = 0.f;
        if (c + 1 < NCHUNK) {
            pn = g_P[base + (c + 1) * DSTATE];
            hn = g_H[base + (c + 1) * DSTATE];
        }
        g_Hin[base + c * DSTATE] = h;
        h  = fmaf(pc, h, hc);
        pc = pn; hc = hn;
    }
}

__global__ void scanC_kernel()
{
    int b = blockIdx.x / NCHUNK;
    int c = blockIdx.x % NCHUNK;
    int s = threadIdx.x;
    float h = g_Hin[(b * NCHUNK + c) * DSTATE + s];
    size_t base = ((size_t)b * SEQ + (size_t)c * CLEN) * DSTATE + s;
    #pragma unroll 4
    for (int i = 0; i < CLEN; i++) {
        float a  = g_Abar[base + (size_t)i * DSTATE];
        float bb = g_Bbar[base + (size_t)i * DSTATE];
        h = fmaf(a, h, bb);
        float yv = g_Cm[base + (size_t)i * DSTATE] * h;
        g_yf[base + (size_t)i * DSTATE] = __float2half_rn(yv);
    }
}

// ---------------------------------------------------------------------------
// Launch
// ---------------------------------------------------------------------------
extern "C" void kernel_launch(void* const* d_in, const int* in_sizes, int n_in,
                              void* d_out, int out_size)
{
    (void)in_sizes; (void)n_in; (void)out_size;
    const float* x    = (const float*)d_in[0];
    const float* cw   = (const float*)d_in[1];
    const float* cb   = (const float*)d_in[2];
    const float* w1   = (const float*)d_in[3];
    const float* b1   = (const float*)d_in[4];
    const float* alog = (const float*)d_in[5];
    const float* w2   = (const float*)d_in[6];
    const float* b2   = (const float*)d_in[7];
    float* out = (float*)d_out;

    float* b1e_p;
    cudaGetSymbolAddress((void**)&b1e_p, g_b1e);

    cudaFuncSetAttribute(gemm1_mma, cudaFuncAttributeMaxDynamicSharedMemorySize, G1_SMEM);
    cudaFuncSetAttribute(gemm2_mma, cudaFuncAttributeMaxDynamicSharedMemorySize, G2_SMEM);

    // 1. conv (fp16 out) + weight prep
    {
        int n = BATCH * SEQ * (DMODEL / 4);
        conv_kernel<<<(n + 255) / 256, 256>>>(x, cw, cb);
        int nw = N_W1E + N_W2;
        wprep_kernel<<<(nw + 255) / 256, 256>>>(w1, b1, w2);
    }
    // 2. proj = xc @ W1eff^T + b1eff  (fp16 single pass, pipelined)
    gemm1_mma<<<M_ROWS / 128, 256, G1_SMEM>>>(b1e_p);

    // 3. elementwise SSM params
    {
        int n = M_ROWS * DSTATE;
        elem_kernel<<<(n + 255) / 256, 256>>>(alog);
    }
    // 4. chunked scan (scanC emits fp16 y)
    scanA_kernel<<<BATCH * NCHUNK, DSTATE>>>();
    scanB_kernel<<<BATCH, DSTATE>>>();
    scanC_kernel<<<BATCH * NCHUNK, DSTATE>>>();

    // 5. out = y @ W2^T + b2  (fp16 single pass)
    {
        dim3 grid(DMODEL / 128, M_ROWS / 128);
        gemm2_mma<<<grid, 256, G2_SMEM>>>(b2, out);
    }
}

// round 15
// speedup vs baseline: 1.0401x; 1.0401x over previous
#include <cuda_runtime.h>
#include <cuda_bf16.h>
#include <cuda_fp16.h>
#include <math.h>
#include <stdint.h>

// Problem constants (fixed by the reference)
#define BATCH   8
#define SEQ     4096
#define DMODEL  1024
#define DSTATE  64
#define PROJ_E  192          // effective rows after folding the pair-mean into W1
#define NCHUNK  64
#define CLEN    64           // SEQ / NCHUNK
#define M_ROWS  (BATCH*SEQ)  // 32768

// ---------------------------------------------------------------------------
// Scratch (static __device__ globals; no allocation in kernel_launch)
// ---------------------------------------------------------------------------
__device__ __half g_xcf[(size_t)M_ROWS * DMODEL];  // conv out, fp16 (67 MB)
__device__ __half g_w1f[(size_t)PROJ_E * DMODEL];  // pre-averaged W1, fp16
__device__ __half g_w2f[(size_t)DMODEL * DSTATE];  // W2, fp16
__device__ __half g_yf [(size_t)M_ROWS * DSTATE];  // y, fp16 (4 MB)
__device__ float g_b1e [PROJ_E];
__device__ float g_Abar[(size_t)M_ROWS * DSTATE];
__device__ float g_Bbar[(size_t)M_ROWS * DSTATE];
__device__ float g_Cm  [(size_t)M_ROWS * DSTATE];
__device__ float g_P   [BATCH * NCHUNK * DSTATE];
__device__ float g_H   [BATCH * NCHUNK * DSTATE];
__device__ float g_Hin [BATCH * NCHUNK * DSTATE];

// ---------------------------------------------------------------------------
// PTX helpers (legacy tensor path: ldmatrix + mma.sync, valid on sm_100 base)
// ---------------------------------------------------------------------------
__device__ __forceinline__ uint32_t smem_u32(const void* p) {
    uint32_t a;
    asm("{ .reg .u64 t; cvta.to.shared.u64 t, %1; cvt.u32.u64 %0, t; }" : "=r"(a) : "l"(p));
    return a;
}
__device__ __forceinline__ void ldsm_x4(uint32_t* r, uint32_t addr) {
    asm volatile("ldmatrix.sync.aligned.m8n8.x4.shared.b16 {%0,%1,%2,%3}, [%4];"
        : "=r"(r[0]), "=r"(r[1]), "=r"(r[2]), "=r"(r[3]) : "r"(addr));
}
__device__ __forceinline__ void mma_f16(float* d, const uint32_t* a, const uint32_t* b) {
    asm volatile("mma.sync.aligned.m16n8k16.row.col.f32.f16.f16.f32 "
        "{%0,%1,%2,%3}, {%4,%5,%6,%7}, {%8,%9}, {%0,%1,%2,%3};"
        : "+f"(d[0]), "+f"(d[1]), "+f"(d[2]), "+f"(d[3])
        : "r"(a[0]), "r"(a[1]), "r"(a[2]), "r"(a[3]), "r"(b[0]), "r"(b[1]));
}
__device__ __forceinline__ void cp16(uint32_t saddr, const void* gaddr) {
    asm volatile("cp.async.cg.shared.global [%0], [%1], 16;" :: "r"(saddr), "l"(gaddr) : "memory");
}
#define CP_COMMIT()  asm volatile("cp.async.commit_group;" ::: "memory")
#define CP_WAIT(n)   asm volatile("cp.async.wait_group %0;" :: "n"(n) : "memory")
// SW128 swizzle on byte offsets (rows of 128 bytes)
#define SWZ(off)   ((uint32_t)(off) ^ ((((uint32_t)(off)) >> 3) & 0x70))

// ---------------------------------------------------------------------------
// 1. Depthwise conv (k=4, pad=(1,1)), last timestep zeroed. Emits fp16.
// ---------------------------------------------------------------------------
__global__ void conv_kernel(const float* __restrict__ x,
                            const float* __restrict__ cw,
                            const float* __restrict__ cb)
{
    const int D4  = DMODEL / 4;
    int idx = blockIdx.x * blockDim.x + threadIdx.x;
    if (idx >= BATCH * SEQ * D4) return;

    int d4 = idx % D4;
    int bt = idx / D4;
    int t  = bt % SEQ;
    int b  = bt / SEQ;
    int d  = d4 * 4;

    float4 acc;
    if (t == SEQ - 1) {
        acc = make_float4(0.f, 0.f, 0.f, 0.f);
    } else {
        acc = *(const float4*)(cb + d);
        float4 w0 = *(const float4*)(cw + (size_t)(d + 0) * 4);
        float4 w1 = *(const float4*)(cw + (size_t)(d + 1) * 4);
        float4 w2 = *(const float4*)(cw + (size_t)(d + 2) * 4);
        float4 w3 = *(const float4*)(cw + (size_t)(d + 3) * 4);
        const float* wa0 = (const float*)&w0;
        const float* wa1 = (const float*)&w1;
        const float* wa2 = (const float*)&w2;
        const float* wa3 = (const float*)&w3;
        const float* xb = x + (size_t)b * SEQ * DMODEL + d;
        #pragma unroll
        for (int j = 0; j < 4; j++) {
            int tt = t - 1 + j;
            if (tt < 0 || tt >= SEQ) continue;
            float4 xv = *(const float4*)(xb + (size_t)tt * DMODEL);
            acc.x = fmaf(wa0[j], xv.x, acc.x);
            acc.y = fmaf(wa1[j], xv.y, acc.y);
            acc.z = fmaf(wa2[j], xv.z, acc.z);
            acc.w = fmaf(wa3[j], xv.w, acc.w);
        }
    }
    __half h[4];
    h[0] = __float2half_rn(acc.x);
    h[1] = __float2half_rn(acc.y);
    h[2] = __float2half_rn(acc.z);
    h[3] = __float2half_rn(acc.w);
    *(uint2*)(g_xcf + (size_t)bt * DMODEL + d) = *(const uint2*)h;
}

// ---------------------------------------------------------------------------
// 1b. Weight prep: fold pair-mean into W1 (320 -> 192 rows) as fp16;
//     W2 as fp16; build effective bias.
// ---------------------------------------------------------------------------
#define N_W1E (PROJ_E * DMODEL)
#define N_W2  (DMODEL * DSTATE)
__global__ void wprep_kernel(const float* __restrict__ w1,
                             const float* __restrict__ b1,
                             const float* __restrict__ w2)
{
    int i = blockIdx.x * blockDim.x + threadIdx.x;
    if (i < N_W1E) {
        int n = i / DMODEL, k = i % DMODEL;
        float v;
        if (n < 64) {
            v = w1[(size_t)n * DMODEL + k];
        } else if (n < 128) {
            int m = 64 + 2 * (n - 64);
            v = 0.5f * (w1[(size_t)m * DMODEL + k] + w1[(size_t)(m + 1) * DMODEL + k]);
        } else {
            int m = 192 + 2 * (n - 128);
            v = 0.5f * (w1[(size_t)m * DMODEL + k] + w1[(size_t)(m + 1) * DMODEL + k]);
        }
        g_w1f[i] = __float2half_rn(v);
    } else if (i < N_W1E + N_W2) {
        int j = i - N_W1E;
        g_w2f[j] = __float2half_rn(w2[j]);
    }
    if (i < PROJ_E) {
        float bv;
        if (i < 64)       bv = b1[i];
        else if (i < 128) bv = 0.5f * (b1[64 + 2 * (i - 64)] + b1[65 + 2 * (i - 64)]);
        else              bv = 0.5f * (b1[192 + 2 * (i - 128)] + b1[193 + 2 * (i - 128)]);
        g_b1e[i] = bv;
    }
}

// ---------------------------------------------------------------------------
// 2. GEMM1 (fp16, single pass) + FUSED elem + scanA in the epilogue.
//    proj-tile = xc[128,1024] @ W1eff[192,1024]^T ; one CTA owns the full
//    192-column row set for 128 consecutive timesteps (= 2 scan chunks).
//    Epilogue: stage accumulators to smem -> elem (bias+softplus+Abar/Bbar)
//    -> write Abar/Bbar/Cm -> local chunk scan -> write P/H.
// ---------------------------------------------------------------------------
#define G1_A 0
#define G1_B 16384
#define G1_STAGE 40960           // A 16KB + B 24KB
#define G1_SMEM (G1_STAGE * 4)   // 163840 bytes >= 128*196*4 = 100352 epilogue
#define EPI_STRIDE 196           // padded row stride (floats); 196 % 32 = 4

__global__ __launch_bounds__(256)
void gemm1_mma(const float* __restrict__ bias, const float* __restrict__ Alog)
{
    extern __shared__ char smem[];
    const uint32_t sb = smem_u32(smem);
    const int tid  = threadIdx.x;
    const int lane = tid & 31;
    const int wid  = tid >> 5;
    const int wm   = (wid >> 2) * 64;   // 0 / 64
    const int wn   = (wid & 3) * 48;    // 0,48,96,144
    const int bm   = blockIdx.x * 128;

    float d[4][6][4];
    #pragma unroll
    for (int i = 0; i < 4; i++)
        #pragma unroll
        for (int j = 0; j < 6; j++)
            #pragma unroll
            for (int c = 0; c < 4; c++) d[i][j][c] = 0.f;

    auto load_chunk = [&](int c) {
        const int k0 = c * 64;                  // fp16 elem offset in K
        const uint32_t s0 = sb + (c & 3) * G1_STAGE;
        #pragma unroll
        for (int i = tid; i < 1024; i += 256) {
            int r = i >> 3, cB = (i & 7) << 4;
            size_t go = (size_t)(bm + r) * DMODEL + k0 + (cB >> 1);
            uint32_t so = SWZ(r * 128 + cB);
            cp16(s0 + G1_A + so, g_xcf + go);
        }
        #pragma unroll
        for (int i = tid; i < 1536; i += 256) {
            int r = i >> 3, cB = (i & 7) << 4;
            size_t go = (size_t)r * DMODEL + k0 + (cB >> 1);
            uint32_t so = SWZ(r * 128 + cB);
            cp16(s0 + G1_B + so, g_w1f + go);
        }
        CP_COMMIT();
    };

    load_chunk(0);
    load_chunk(1);
    load_chunk(2);

    const int T = 16;
    for (int c = 0; c < T; c++) {
        if (c + 3 < T)      { CP_WAIT(2); }
        else if (c + 2 < T) { CP_WAIT(1); }
        else                { CP_WAIT(0); }
        __syncthreads();
        if (c + 3 < T) load_chunk(c + 3);

        const uint32_t sA = sb + (c & 3) * G1_STAGE;
        #pragma unroll
        for (int ks = 0; ks < 4; ks++) {
            const int kb = ks * 32;     // byte col of this k16 step
            const int mi = lane >> 3;
            const int col = kb + ((mi >> 1) << 4);
            uint32_t bh[6][2];
            #pragma unroll
            for (int jj = 0; jj < 3; jj++) {
                int row = wn + jj * 16 + ((mi & 1) << 3) + (lane & 7);
                uint32_t so = SWZ(row * 128 + col);
                uint32_t r4[4];
                ldsm_x4(r4, sA + G1_B + so);
                bh[2*jj][0] = r4[0]; bh[2*jj+1][0] = r4[1];
                bh[2*jj][1] = r4[2]; bh[2*jj+1][1] = r4[3];
            }
            uint32_t ah[4][4];
            #pragma unroll
            for (int i = 0; i < 4; i++) {
                int row = wm + i * 16 + ((mi & 1) << 3) + (lane & 7);
                uint32_t so = SWZ(row * 128 + col);
                ldsm_x4(ah[i], sA + G1_A + so);
            }
            #pragma unroll
            for (int i = 0; i < 4; i++)
                #pragma unroll
                for (int j = 0; j < 6; j++) mma_f16(d[i][j], ah[i], bh[j]);
        }
    }

    // ---- Fused epilogue ----
    __syncthreads();                       // pipeline smem now dead
    float* sp = (float*)smem;              // [128][EPI_STRIDE]
    const int gid = lane >> 2, tig = lane & 3;
    #pragma unroll
    for (int i = 0; i < 4; i++) {
        int row0 = wm + i * 16 + gid;
        #pragma unroll
        for (int j = 0; j < 6; j++) {
            int col = wn + j * 8 + tig * 2;
            sp[row0 * EPI_STRIDE + col]           = d[i][j][0];
            sp[row0 * EPI_STRIDE + col + 1]       = d[i][j][1];
            sp[(row0 + 8) * EPI_STRIDE + col]     = d[i][j][2];
            sp[(row0 + 8) * EPI_STRIDE + col + 1] = d[i][j][3];
        }
    }
    __syncthreads();

    // elem phase: thread -> (s = tid&63, row group = tid>>6 of 32 rows)
    {
        const int s  = tid & 63;
        const int rg = tid >> 6;
        const float bd = bias[s], bbi = bias[64 + s], bc = bias[128 + s];
        const float A = -expf(Alog[s]);
        const float invA = 1.f / A;
        const bool taylor = fabsf(A) < 1e-4f;
        #pragma unroll 4
        for (int r = 0; r < 32; r++) {
            int row = rg * 32 + r;
            float delta = sp[row * EPI_STRIDE + s]       + bd;
            float Bm    = sp[row * EPI_STRIDE + 64 + s]  + bbi;
            float Cm    = sp[row * EPI_STRIDE + 128 + s] + bc;

            float spv = fmaxf(delta, 0.f) + log1pf(expf(-fabsf(delta)));
            float dA = spv * A;
            float Abar = expf(dA);
            float scale = taylor ? (1.f + dA * 0.5f + dA * dA * (1.f / 6.f))
                                 : (Abar - 1.f) * invA;
            float Bbar = scale * Bm;

            size_t o = (size_t)(bm + row) * DSTATE + s;
            g_Abar[o] = Abar;
            g_Bbar[o] = Bbar;
            g_Cm[o]   = Cm;
            sp[row * EPI_STRIDE + s]      = Abar;
            sp[row * EPI_STRIDE + 64 + s] = Bbar;
        }
    }
    __syncthreads();

    // scanA phase: 128 threads -> (chunk = tid>>6 in {0,1}, s = tid&63)
    if (tid < 128) {
        const int ch = tid >> 6;
        const int s  = tid & 63;
        float h = 0.f, p = 1.f;
        #pragma unroll 4
        for (int i = 0; i < CLEN; i++) {
            int row = ch * 64 + i;
            float a  = sp[row * EPI_STRIDE + s];
            float bb = sp[row * EPI_STRIDE + 64 + s];
            h = fmaf(a, h, bb);
            p *= a;
        }
        int o = (blockIdx.x * 2 + ch) * DSTATE + s;
        g_P[o] = p;
        g_H[o] = h;
    }
}

// ---------------------------------------------------------------------------
// 2b. GEMM2 (fp16, single pass): out[M,1024] = y[M,64] @ W2[1024,64]^T + b2
//    CTA tile 128x128, K=64 in one shot. 8 warps (2m x 4n), warp tile 64x32.
// ---------------------------------------------------------------------------
#define G2_A 0
#define G2_B 16384
#define G2_SMEM 32768

__global__ __launch_bounds__(256)
void gemm2_mma(const float* __restrict__ bias, float* __restrict__ out)
{
    extern __shared__ char smem[];
    const uint32_t sb = smem_u32(smem);
    const int tid  = threadIdx.x;
    const int lane = tid & 31;
    const int wid  = tid >> 5;
    const int wm   = (wid >> 2) * 64;
    const int wn   = (wid & 3) * 32;
    const int bm   = blockIdx.y * 128;
    const int bn   = blockIdx.x * 128;

    float d[4][4][4];
    #pragma unroll
    for (int i = 0; i < 4; i++)
        #pragma unroll
        for (int j = 0; j < 4; j++)
            #pragma unroll
            for (int c = 0; c < 4; c++) d[i][j][c] = 0.f;

    #pragma unroll
    for (int i = tid; i < 1024; i += 256) {
        int r = i >> 3, cB = (i & 7) << 4;
        size_t go = (size_t)(bm + r) * DSTATE + (cB >> 1);
        uint32_t so = SWZ(r * 128 + cB);
        cp16(sb + G2_A + so, g_yf + go);
    }
    #pragma unroll
    for (int i = tid; i < 1024; i += 256) {
        int r = i >> 3, cB = (i & 7) << 4;
        size_t go = (size_t)(bn + r) * DSTATE + (cB >> 1);
        uint32_t so = SWZ(r * 128 + cB);
        cp16(sb + G2_B + so, g_w2f + go);
    }
    CP_COMMIT();
    CP_WAIT(0);
    __syncthreads();

    #pragma unroll
    for (int ks = 0; ks < 4; ks++) {
        const int kb = ks * 32;
        const int mi = lane >> 3;
        uint32_t bh[4][2];
        {
            int row = wn + ((mi & 1) << 3) + (lane & 7);
            int col = kb + ((mi >> 1) << 4);
            uint32_t so = SWZ(row * 128 + col);
            uint32_t r4[4];
            ldsm_x4(r4, sb + G2_B + so);
            bh[0][0] = r4[0]; bh[1][0] = r4[1]; bh[0][1] = r4[2]; bh[1][1] = r4[3];
            uint32_t so2 = SWZ((row + 16) * 128 + col);
            ldsm_x4(r4, sb + G2_B + so2);
            bh[2][0] = r4[0]; bh[3][0] = r4[1]; bh[2][1] = r4[2]; bh[3][1] = r4[3];
        }
        uint32_t ah[4][4];
        #pragma unroll
        for (int i = 0; i < 4; i++) {
            int row = wm + i * 16 + ((mi & 1) << 3) + (lane & 7);
            int col = kb + ((mi >> 1) << 4);
            uint32_t so = SWZ(row * 128 + col);
            ldsm_x4(ah[i], sb + G2_A + so);
        }
        #pragma unroll
        for (int i = 0; i < 4; i++)
            #pragma unroll
            for (int j = 0; j < 4; j++) mma_f16(d[i][j], ah[i], bh[j]);
    }

    const int gid = lane >> 2, tig = lane & 3;
    #pragma unroll
    for (int i = 0; i < 4; i++) {
        int row0 = bm + wm + i * 16 + gid;
        #pragma unroll
        for (int j = 0; j < 4; j++) {
            int col = bn + wn + j * 8 + tig * 2;
            float b0 = bias[col], b1 = bias[col + 1];
            float2 v0 = make_float2(d[i][j][0] + b0, d[i][j][1] + b1);
            float2 v1 = make_float2(d[i][j][2] + b0, d[i][j][3] + b1);
            *(float2*)(out + (size_t)row0 * DMODEL + col)       = v0;
            *(float2*)(out + (size_t)(row0 + 8) * DMODEL + col) = v1;
        }
    }
}

// ---------------------------------------------------------------------------
// 4. Cross-chunk scan + final scan
// ---------------------------------------------------------------------------
__global__ void scanB_kernel()
{
    int b = blockIdx.x;
    int s = threadIdx.x;
    int base = b * NCHUNK * DSTATE + s;
    float h  = 0.f;
    float pc = g_P[base];
    float hc = g_H[base];
    for (int c = 0; c < NCHUNK; c++) {
        float pn = 0.f, hn = 0.f;
        if (c + 1 < NCHUNK) {
            pn = g_P[base + (c + 1) * DSTATE];
            hn = g_H[base + (c + 1) * DSTATE];
        }
        g_Hin[base + c * DSTATE] = h;
        h  = fmaf(pc, h, hc);
        pc = pn; hc = hn;
    }
}

__global__ void scanC_kernel()
{
    int b = blockIdx.x / NCHUNK;
    int c = blockIdx.x % NCHUNK;
    int s = threadIdx.x;
    float h = g_Hin[(b * NCHUNK + c) * DSTATE + s];
    size_t base = ((size_t)b * SEQ + (size_t)c * CLEN) * DSTATE + s;
    #pragma unroll 4
    for (int i = 0; i < CLEN; i++) {
        float a  = g_Abar[base + (size_t)i * DSTATE];
        float bb = g_Bbar[base + (size_t)i * DSTATE];
        h = fmaf(a, h, bb);
        float yv = g_Cm[base + (size_t)i * DSTATE] * h;
        g_yf[base + (size_t)i * DSTATE] = __float2half_rn(yv);
    }
}

// ---------------------------------------------------------------------------
// Launch
// ---------------------------------------------------------------------------
extern "C" void kernel_launch(void* const* d_in, const int* in_sizes, int n_in,
                              void* d_out, int out_size)
{
    (void)in_sizes; (void)n_in; (void)out_size;
    const float* x    = (const float*)d_in[0];
    const float* cw   = (const float*)d_in[1];
    const float* cb   = (const float*)d_in[2];
    const float* w1   = (const float*)d_in[3];
    const float* b1   = (const float*)d_in[4];
    const float* alog = (const float*)d_in[5];
    const float* w2   = (const float*)d_in[6];
    const float* b2   = (const float*)d_in[7];
    float* out = (float*)d_out;

    float* b1e_p;
    cudaGetSymbolAddress((void**)&b1e_p, g_b1e);

    cudaFuncSetAttribute(gemm1_mma, cudaFuncAttributeMaxDynamicSharedMemorySize, G1_SMEM);
    cudaFuncSetAttribute(gemm2_mma, cudaFuncAttributeMaxDynamicSharedMemorySize, G2_SMEM);

    // 1. conv (fp16 out) + weight prep
    {
        int n = BATCH * SEQ * (DMODEL / 4);
        conv_kernel<<<(n + 255) / 256, 256>>>(x, cw, cb);
        int nw = N_W1E + N_W2;
        wprep_kernel<<<(nw + 255) / 256, 256>>>(w1, b1, w2);
    }
    // 2. gemm1 + fused elem + fused scanA
    gemm1_mma<<<M_ROWS / 128, 256, G1_SMEM>>>(b1e_p, alog);

    // 3. cross-chunk scan + final scan (emits fp16 y)
    scanB_kernel<<<BATCH, DSTATE>>>();
    scanC_kernel<<<BATCH * NCHUNK, DSTATE>>>();

    // 4. out = y @ W2^T + b2  (fp16 single pass)
    {
        dim3 grid(DMODEL / 128, M_ROWS / 128);
        gemm2_mma<<<grid, 256, G2_SMEM>>>(b2, out);
    }
}

// round 16
// speedup vs baseline: 1.0651x; 1.0241x over previous
#include <cuda_runtime.h>
#include <cuda_bf16.h>
#include <cuda_fp16.h>
#include <math.h>
#include <stdint.h>

// Problem constants (fixed by the reference)
#define BATCH   8
#define SEQ     4096
#define DMODEL  1024
#define DSTATE  64
#define PROJ_E  192          // effective rows after folding the pair-mean into W1
#define NCHUNK  64
#define CLEN    64           // SEQ / NCHUNK
#define M_ROWS  (BATCH*SEQ)  // 32768

// ---------------------------------------------------------------------------
// Scratch (static __device__ globals; no allocation in kernel_launch)
// ---------------------------------------------------------------------------
__device__ __half g_xcf[(size_t)M_ROWS * DMODEL];  // conv out, fp16 (67 MB)
__device__ __half g_w1f[(size_t)PROJ_E * DMODEL];  // pre-averaged W1, fp16
__device__ __half g_w2f[(size_t)DMODEL * DSTATE];  // W2, fp16
__device__ __half g_yf [(size_t)M_ROWS * DSTATE];  // y, fp16 (4 MB)
__device__ float g_b1e [PROJ_E];
__device__ float g_Abar[(size_t)M_ROWS * DSTATE];
__device__ float g_Bbar[(size_t)M_ROWS * DSTATE];
__device__ float g_Cm  [(size_t)M_ROWS * DSTATE];
__device__ float g_P   [BATCH * NCHUNK * DSTATE];
__device__ float g_H   [BATCH * NCHUNK * DSTATE];
__device__ float g_Hin [BATCH * NCHUNK * DSTATE];

// ---------------------------------------------------------------------------
// PTX helpers (legacy tensor path: ldmatrix + mma.sync, valid on sm_100 base)
// ---------------------------------------------------------------------------
__device__ __forceinline__ uint32_t smem_u32(const void* p) {
    uint32_t a;
    asm("{ .reg .u64 t; cvta.to.shared.u64 t, %1; cvt.u32.u64 %0, t; }" : "=r"(a) : "l"(p));
    return a;
}
__device__ __forceinline__ void ldsm_x4(uint32_t* r, uint32_t addr) {
    asm volatile("ldmatrix.sync.aligned.m8n8.x4.shared.b16 {%0,%1,%2,%3}, [%4];"
        : "=r"(r[0]), "=r"(r[1]), "=r"(r[2]), "=r"(r[3]) : "r"(addr));
}
__device__ __forceinline__ void mma_f16(float* d, const uint32_t* a, const uint32_t* b) {
    asm volatile("mma.sync.aligned.m16n8k16.row.col.f32.f16.f16.f32 "
        "{%0,%1,%2,%3}, {%4,%5,%6,%7}, {%8,%9}, {%0,%1,%2,%3};"
        : "+f"(d[0]), "+f"(d[1]), "+f"(d[2]), "+f"(d[3])
        : "r"(a[0]), "r"(a[1]), "r"(a[2]), "r"(a[3]), "r"(b[0]), "r"(b[1]));
}
__device__ __forceinline__ void cp16(uint32_t saddr, const void* gaddr) {
    asm volatile("cp.async.cg.shared.global [%0], [%1], 16;" :: "r"(saddr), "l"(gaddr) : "memory");
}
#define CP_COMMIT()  asm volatile("cp.async.commit_group;" ::: "memory")
#define CP_WAIT(n)   asm volatile("cp.async.wait_group %0;" :: "n"(n) : "memory")
// SW128 swizzle on byte offsets (rows of 128 bytes)
#define SWZ(off)   ((uint32_t)(off) ^ ((((uint32_t)(off)) >> 3) & 0x70))

// ---------------------------------------------------------------------------
// 1. Depthwise conv (k=4, pad=(1,1)), last timestep zeroed. Emits fp16.
// ---------------------------------------------------------------------------
__global__ void conv_kernel(const float* __restrict__ x,
                            const float* __restrict__ cw,
                            const float* __restrict__ cb)
{
    const int D4  = DMODEL / 4;
    int idx = blockIdx.x * blockDim.x + threadIdx.x;
    if (idx >= BATCH * SEQ * D4) return;

    int d4 = idx % D4;
    int bt = idx / D4;
    int t  = bt % SEQ;
    int b  = bt / SEQ;
    int d  = d4 * 4;

    float4 acc;
    if (t == SEQ - 1) {
        acc = make_float4(0.f, 0.f, 0.f, 0.f);
    } else {
        acc = *(const float4*)(cb + d);
        float4 w0 = *(const float4*)(cw + (size_t)(d + 0) * 4);
        float4 w1 = *(const float4*)(cw + (size_t)(d + 1) * 4);
        float4 w2 = *(const float4*)(cw + (size_t)(d + 2) * 4);
        float4 w3 = *(const float4*)(cw + (size_t)(d + 3) * 4);
        const float* wa0 = (const float*)&w0;
        const float* wa1 = (const float*)&w1;
        const float* wa2 = (const float*)&w2;
        const float* wa3 = (const float*)&w3;
        const float* xb = x + (size_t)b * SEQ * DMODEL + d;
        #pragma unroll
        for (int j = 0; j < 4; j++) {
            int tt = t - 1 + j;
            if (tt < 0 || tt >= SEQ) continue;
            float4 xv = *(const float4*)(xb + (size_t)tt * DMODEL);
            acc.x = fmaf(wa0[j], xv.x, acc.x);
            acc.y = fmaf(wa1[j], xv.y, acc.y);
            acc.z = fmaf(wa2[j], xv.z, acc.z);
            acc.w = fmaf(wa3[j], xv.w, acc.w);
        }
    }
    __half h[4];
    h[0] = __float2half_rn(acc.x);
    h[1] = __float2half_rn(acc.y);
    h[2] = __float2half_rn(acc.z);
    h[3] = __float2half_rn(acc.w);
    *(uint2*)(g_xcf + (size_t)bt * DMODEL + d) = *(const uint2*)h;
}

// ---------------------------------------------------------------------------
// 1b. Weight prep: fold pair-mean into W1 (320 -> 192 rows) as fp16;
//     W2 as fp16; build effective bias.
// ---------------------------------------------------------------------------
#define N_W1E (PROJ_E * DMODEL)
#define N_W2  (DMODEL * DSTATE)
__global__ void wprep_kernel(const float* __restrict__ w1,
                             const float* __restrict__ b1,
                             const float* __restrict__ w2)
{
    int i = blockIdx.x * blockDim.x + threadIdx.x;
    if (i < N_W1E) {
        int n = i / DMODEL, k = i % DMODEL;
        float v;
        if (n < 64) {
            v = w1[(size_t)n * DMODEL + k];
        } else if (n < 128) {
            int m = 64 + 2 * (n - 64);
            v = 0.5f * (w1[(size_t)m * DMODEL + k] + w1[(size_t)(m + 1) * DMODEL + k]);
        } else {
            int m = 192 + 2 * (n - 128);
            v = 0.5f * (w1[(size_t)m * DMODEL + k] + w1[(size_t)(m + 1) * DMODEL + k]);
        }
        g_w1f[i] = __float2half_rn(v);
    } else if (i < N_W1E + N_W2) {
        int j = i - N_W1E;
        g_w2f[j] = __float2half_rn(w2[j]);
    }
    if (i < PROJ_E) {
        float bv;
        if (i < 64)       bv = b1[i];
        else if (i < 128) bv = 0.5f * (b1[64 + 2 * (i - 64)] + b1[65 + 2 * (i - 64)]);
        else              bv = 0.5f * (b1[192 + 2 * (i - 128)] + b1[193 + 2 * (i - 128)]);
        g_b1e[i] = bv;
    }
}

// ---------------------------------------------------------------------------
// 2. GEMM1 (fp16, single pass) + FUSED elem + scanA in the epilogue.
// ---------------------------------------------------------------------------
#define G1_A 0
#define G1_B 16384
#define G1_STAGE 40960           // A 16KB + B 24KB
#define G1_SMEM (G1_STAGE * 4)   // 163840 bytes >= 128*196*4 = 100352 epilogue
#define EPI_STRIDE 196           // padded row stride (floats)

__global__ __launch_bounds__(256)
void gemm1_mma(const float* __restrict__ bias, const float* __restrict__ Alog)
{
    extern __shared__ char smem[];
    const uint32_t sb = smem_u32(smem);
    const int tid  = threadIdx.x;
    const int lane = tid & 31;
    const int wid  = tid >> 5;
    const int wm   = (wid >> 2) * 64;   // 0 / 64
    const int wn   = (wid & 3) * 48;    // 0,48,96,144
    const int bm   = blockIdx.x * 128;

    float d[4][6][4];
    #pragma unroll
    for (int i = 0; i < 4; i++)
        #pragma unroll
        for (int j = 0; j < 6; j++)
            #pragma unroll
            for (int c = 0; c < 4; c++) d[i][j][c] = 0.f;

    auto load_chunk = [&](int c) {
        const int k0 = c * 64;                  // fp16 elem offset in K
        const uint32_t s0 = sb + (c & 3) * G1_STAGE;
        #pragma unroll
        for (int i = tid; i < 1024; i += 256) {
            int r = i >> 3, cB = (i & 7) << 4;
            size_t go = (size_t)(bm + r) * DMODEL + k0 + (cB >> 1);
            uint32_t so = SWZ(r * 128 + cB);
            cp16(s0 + G1_A + so, g_xcf + go);
        }
        #pragma unroll
        for (int i = tid; i < 1536; i += 256) {
            int r = i >> 3, cB = (i & 7) << 4;
            size_t go = (size_t)r * DMODEL + k0 + (cB >> 1);
            uint32_t so = SWZ(r * 128 + cB);
            cp16(s0 + G1_B + so, g_w1f + go);
        }
        CP_COMMIT();
    };

    load_chunk(0);
    load_chunk(1);
    load_chunk(2);

    const int T = 16;
    for (int c = 0; c < T; c++) {
        if (c + 3 < T)      { CP_WAIT(2); }
        else if (c + 2 < T) { CP_WAIT(1); }
        else                { CP_WAIT(0); }
        __syncthreads();
        if (c + 3 < T) load_chunk(c + 3);

        const uint32_t sA = sb + (c & 3) * G1_STAGE;
        #pragma unroll
        for (int ks = 0; ks < 4; ks++) {
            const int kb = ks * 32;     // byte col of this k16 step
            const int mi = lane >> 3;
            const int col = kb + ((mi >> 1) << 4);
            uint32_t bh[6][2];
            #pragma unroll
            for (int jj = 0; jj < 3; jj++) {
                int row = wn + jj * 16 + ((mi & 1) << 3) + (lane & 7);
                uint32_t so = SWZ(row * 128 + col);
                uint32_t r4[4];
                ldsm_x4(r4, sA + G1_B + so);
                bh[2*jj][0] = r4[0]; bh[2*jj+1][0] = r4[1];
                bh[2*jj][1] = r4[2]; bh[2*jj+1][1] = r4[3];
            }
            uint32_t ah[4][4];
            #pragma unroll
            for (int i = 0; i < 4; i++) {
                int row = wm + i * 16 + ((mi & 1) << 3) + (lane & 7);
                uint32_t so = SWZ(row * 128 + col);
                ldsm_x4(ah[i], sA + G1_A + so);
            }
            #pragma unroll
            for (int i = 0; i < 4; i++)
                #pragma unroll
                for (int j = 0; j < 6; j++) mma_f16(d[i][j], ah[i], bh[j]);
        }
    }

    // ---- Fused epilogue ----
    __syncthreads();                       // pipeline smem now dead
    float* sp = (float*)smem;              // [128][EPI_STRIDE]
    const int gid = lane >> 2, tig = lane & 3;
    #pragma unroll
    for (int i = 0; i < 4; i++) {
        int row0 = wm + i * 16 + gid;
        #pragma unroll
        for (int j = 0; j < 6; j++) {
            int col = wn + j * 8 + tig * 2;
            sp[row0 * EPI_STRIDE + col]           = d[i][j][0];
            sp[row0 * EPI_STRIDE + col + 1]       = d[i][j][1];
            sp[(row0 + 8) * EPI_STRIDE + col]     = d[i][j][2];
            sp[(row0 + 8) * EPI_STRIDE + col + 1] = d[i][j][3];
        }
    }
    __syncthreads();

    // elem phase
    {
        const int s  = tid & 63;
        const int rg = tid >> 6;
        const float bd = bias[s], bbi = bias[64 + s], bc = bias[128 + s];
        const float A = -expf(Alog[s]);
        const float invA = 1.f / A;
        const bool taylor = fabsf(A) < 1e-4f;
        #pragma unroll 4
        for (int r = 0; r < 32; r++) {
            int row = rg * 32 + r;
            float delta = sp[row * EPI_STRIDE + s]       + bd;
            float Bm    = sp[row * EPI_STRIDE + 64 + s]  + bbi;
            float Cm    = sp[row * EPI_STRIDE + 128 + s] + bc;

            float spv = fmaxf(delta, 0.f) + log1pf(expf(-fabsf(delta)));
            float dA = spv * A;
            float Abar = expf(dA);
            float scale = taylor ? (1.f + dA * 0.5f + dA * dA * (1.f / 6.f))
                                 : (Abar - 1.f) * invA;
            float Bbar = scale * Bm;

            size_t o = (size_t)(bm + row) * DSTATE + s;
            g_Abar[o] = Abar;
            g_Bbar[o] = Bbar;
            g_Cm[o]   = Cm;
            sp[row * EPI_STRIDE + s]      = Abar;
            sp[row * EPI_STRIDE + 64 + s] = Bbar;
        }
    }
    __syncthreads();

    // scanA phase: 128 threads -> (chunk = tid>>6 in {0,1}, s = tid&63)
    if (tid < 128) {
        const int ch = tid >> 6;
        const int s  = tid & 63;
        float h = 0.f, p = 1.f;
        #pragma unroll 4
        for (int i = 0; i < CLEN; i++) {
            int row = ch * 64 + i;
            float a  = sp[row * EPI_STRIDE + s];
            float bb = sp[row * EPI_STRIDE + 64 + s];
            h = fmaf(a, h, bb);
            p *= a;
        }
        int o = (blockIdx.x * 2 + ch) * DSTATE + s;
        g_P[o] = p;
        g_H[o] = h;
    }
}

// ---------------------------------------------------------------------------
// 2b. GEMM2 (fp16, single pass): out[M,1024] = y[M,64] @ W2[1024,64]^T + b2
// ---------------------------------------------------------------------------
#define G2_A 0
#define G2_B 16384
#define G2_SMEM 32768

__global__ __launch_bounds__(256)
void gemm2_mma(const float* __restrict__ bias, float* __restrict__ out)
{
    extern __shared__ char smem[];
    const uint32_t sb = smem_u32(smem);
    const int tid  = threadIdx.x;
    const int lane = tid & 31;
    const int wid  = tid >> 5;
    const int wm   = (wid >> 2) * 64;
    const int wn   = (wid & 3) * 32;
    const int bm   = blockIdx.y * 128;
    const int bn   = blockIdx.x * 128;

    float d[4][4][4];
    #pragma unroll
    for (int i = 0; i < 4; i++)
        #pragma unroll
        for (int j = 0; j < 4; j++)
            #pragma unroll
            for (int c = 0; c < 4; c++) d[i][j][c] = 0.f;

    #pragma unroll
    for (int i = tid; i < 1024; i += 256) {
        int r = i >> 3, cB = (i & 7) << 4;
        size_t go = (size_t)(bm + r) * DSTATE + (cB >> 1);
        uint32_t so = SWZ(r * 128 + cB);
        cp16(sb + G2_A + so, g_yf + go);
    }
    #pragma unroll
    for (int i = tid; i < 1024; i += 256) {
        int r = i >> 3, cB = (i & 7) << 4;
        size_t go = (size_t)(bn + r) * DSTATE + (cB >> 1);
        uint32_t so = SWZ(r * 128 + cB);
        cp16(sb + G2_B + so, g_w2f + go);
    }
    CP_COMMIT();
    CP_WAIT(0);
    __syncthreads();

    #pragma unroll
    for (int ks = 0; ks < 4; ks++) {
        const int kb = ks * 32;
        const int mi = lane >> 3;
        uint32_t bh[4][2];
        {
            int row = wn + ((mi & 1) << 3) + (lane & 7);
            int col = kb + ((mi >> 1) << 4);
            uint32_t so = SWZ(row * 128 + col);
            uint32_t r4[4];
            ldsm_x4(r4, sb + G2_B + so);
            bh[0][0] = r4[0]; bh[1][0] = r4[1]; bh[0][1] = r4[2]; bh[1][1] = r4[3];
            uint32_t so2 = SWZ((row + 16) * 128 + col);
            ldsm_x4(r4, sb + G2_B + so2);
            bh[2][0] = r4[0]; bh[3][0] = r4[1]; bh[2][1] = r4[2]; bh[3][1] = r4[3];
        }
        uint32_t ah[4][4];
        #pragma unroll
        for (int i = 0; i < 4; i++) {
            int row = wm + i * 16 + ((mi & 1) << 3) + (lane & 7);
            int col = kb + ((mi >> 1) << 4);
            uint32_t so = SWZ(row * 128 + col);
            ldsm_x4(ah[i], sb + G2_A + so);
        }
        #pragma unroll
        for (int i = 0; i < 4; i++)
            #pragma unroll
            for (int j = 0; j < 4; j++) mma_f16(d[i][j], ah[i], bh[j]);
    }

    const int gid = lane >> 2, tig = lane & 3;
    #pragma unroll
    for (int i = 0; i < 4; i++) {
        int row0 = bm + wm + i * 16 + gid;
        #pragma unroll
        for (int j = 0; j < 4; j++) {
            int col = bn + wn + j * 8 + tig * 2;
            float b0 = bias[col], b1 = bias[col + 1];
            float2 v0 = make_float2(d[i][j][0] + b0, d[i][j][1] + b1);
            float2 v1 = make_float2(d[i][j][2] + b0, d[i][j][3] + b1);
            *(float2*)(out + (size_t)row0 * DMODEL + col)       = v0;
            *(float2*)(out + (size_t)(row0 + 8) * DMODEL + col) = v1;
        }
    }
}

// ---------------------------------------------------------------------------
// 4a. Cross-chunk scan: Kogge-Stone over 64 chunks, in smem.
//     Grid = 32 (8 batches x 4 state-groups), block = 1024 (64 chunks x 16 s).
//     Combine (earlier e1, later e2): p = p1*p2, h = p2*h1 + h2.
// ---------------------------------------------------------------------------
__global__ __launch_bounds__(1024)
void scanB_kernel()
{
    __shared__ float sP[NCHUNK][17];
    __shared__ float sH[NCHUNK][17];
    const int b  = blockIdx.x >> 2;
    const int sg = (blockIdx.x & 3) * 16;
    const int c  = threadIdx.x >> 4;      // 0..63
    const int sl = threadIdx.x & 15;      // 0..15
    const int gi = (b * NCHUNK + c) * DSTATE + sg + sl;

    float p = g_P[gi], h = g_H[gi];
    sP[c][sl] = p; sH[c][sl] = h;
    __syncthreads();

    #pragma unroll
    for (int dstep = 1; dstep < NCHUNK; dstep <<= 1) {
        float pp = 1.f, hp = 0.f;
        bool act = (c >= dstep);
        if (act) { pp = sP[c - dstep][sl]; hp = sH[c - dstep][sl]; }
        __syncthreads();
        if (act) {
            h = fmaf(p, hp, h);
            p = p * pp;
            sP[c][sl] = p; sH[c][sl] = h;
        }
        __syncthreads();
    }

    // exclusive: Hin[c] = inclusive[c-1].h, 0 for c = 0
    float hin = (c == 0) ? 0.f : sH[c - 1][sl];
    g_Hin[gi] = hin;
}

// ---------------------------------------------------------------------------
// 4b. Final scan: 256-thread blocks, 4 chunks per block.
// ---------------------------------------------------------------------------
__global__ void scanC_kernel()
{
    int gb = blockIdx.x;                 // 0..127
    int cl = threadIdx.x >> 6;           // 0..3
    int s  = threadIdx.x & 63;
    int b  = gb >> 4;
    int c  = (gb & 15) * 4 + cl;

    float h = g_Hin[(b * NCHUNK + c) * DSTATE + s];
    size_t base = ((size_t)b * SEQ + (size_t)c * CLEN) * DSTATE + s;
    #pragma unroll 4
    for (int i = 0; i < CLEN; i++) {
        float a  = g_Abar[base + (size_t)i * DSTATE];
        float bb = g_Bbar[base + (size_t)i * DSTATE];
        h = fmaf(a, h, bb);
        float yv = g_Cm[base + (size_t)i * DSTATE] * h;
        g_yf[base + (size_t)i * DSTATE] = __float2half_rn(yv);
    }
}

// ---------------------------------------------------------------------------
// Launch
// ---------------------------------------------------------------------------
extern "C" void kernel_launch(void* const* d_in, const int* in_sizes, int n_in,
                              void* d_out, int out_size)
{
    (void)in_sizes; (void)n_in; (void)out_size;
    const float* x    = (const float*)d_in[0];
    const float* cw   = (const float*)d_in[1];
    const float* cb   = (const float*)d_in[2];
    const float* w1   = (const float*)d_in[3];
    const float* b1   = (const float*)d_in[4];
    const float* alog = (const float*)d_in[5];
    const float* w2   = (const float*)d_in[6];
    const float* b2   = (const float*)d_in[7];
    float* out = (float*)d_out;

    float* b1e_p;
    cudaGetSymbolAddress((void**)&b1e_p, g_b1e);

    cudaFuncSetAttribute(gemm1_mma, cudaFuncAttributeMaxDynamicSharedMemorySize, G1_SMEM);
    cudaFuncSetAttribute(gemm2_mma, cudaFuncAttributeMaxDynamicSharedMemorySize, G2_SMEM);

    // 1. conv (fp16 out) + weight prep
    {
        int n = BATCH * SEQ * (DMODEL / 4);
        conv_kernel<<<(n + 255) / 256, 256>>>(x, cw, cb);
        int nw = N_W1E + N_W2;
        wprep_kernel<<<(nw + 255) / 256, 256>>>(w1, b1, w2);
    }
    // 2. gemm1 + fused elem + fused scanA
    gemm1_mma<<<M_ROWS / 128, 256, G1_SMEM>>>(b1e_p, alog);

    // 3. cross-chunk Kogge-Stone scan + final scan (emits fp16 y)
    scanB_kernel<<<BATCH * 4, 1024>>>();
    scanC_kernel<<<BATCH * NCHUNK / 4, 256>>>();

    // 4. out = y @ W2^T + b2  (fp16 single pass)
    {
        dim3 grid(DMODEL / 128, M_ROWS / 128);
        gemm2_mma<<<grid, 256, G2_SMEM>>>(b2, out);
    }
}